// round 2
// baseline (speedup 1.0000x reference)
#include <cuda_runtime.h>
#include <math.h>

#define TT 256
#define BB 64
#define HH 1024
#define G4 4096
#define MM (TT*BB)

typedef unsigned long long u64;

// ---------------------------------------------------------------------------
// Packed f32x2 helpers (Blackwell FFMA2 path — 2 FMA per instruction)
// ---------------------------------------------------------------------------
__device__ __forceinline__ u64 pack2(float lo, float hi) {
    u64 r; asm("mov.b64 %0, {%1, %2};" : "=l"(r) : "f"(lo), "f"(hi)); return r;
}
__device__ __forceinline__ void unpack2(u64 v, float& lo, float& hi) {
    asm("mov.b64 {%0, %1}, %2;" : "=f"(lo), "=f"(hi) : "l"(v));
}
__device__ __forceinline__ void fma2(u64& d, u64 a, u64 b) {
    asm("fma.rn.f32x2 %0, %1, %2, %0;" : "+l"(d) : "l"(a), "l"(b));
}

// ---------------------------------------------------------------------------
// Scratch (device globals: allocation-free per harness rules)
// ---------------------------------------------------------------------------
__device__ float g_xg[(size_t)MM * G4];     // (T,B,4H) precomputed input gates
__device__ float g_out5[(size_t)MM * HH];   // layer-5 output (incl. residual)
__device__ float g_h[2][BB * HH];           // ping-pong hidden state
__device__ float g_c[BB * HH];              // cell state

__global__ void init_state_kernel() {
    int i = blockIdx.x * blockDim.x + threadIdx.x;
    if (i < BB * HH) {
        g_h[0][i] = 0.f;
        g_h[1][i] = 0.f;
        g_c[i]    = 0.f;
    }
}

// ---------------------------------------------------------------------------
// Input GEMM: XG[m][n] = sum_k X[m][k]*W[n][k] + b1[n] + b2[n]
// M=16384, N=4096, K=1024. 128x128 CTA tile, BK=8, 8x8 per thread,
// micro-kernel in packed f32x2 (8 x 4 f32x2 accumulators).
// ---------------------------------------------------------------------------
__global__ __launch_bounds__(256)
void gemm_xg_kernel(const float* __restrict__ X,
                    const float* __restrict__ W,
                    const float* __restrict__ b1,
                    const float* __restrict__ b2,
                    float* __restrict__ XG)
{
    __shared__ float As[8][128];
    __shared__ float Bs[8][128];

    const int tid = threadIdx.x;
    const int m0 = blockIdx.y * 128;
    const int n0 = blockIdx.x * 128;

    const int lr = tid >> 1;          // 0..127
    const int lc = (tid & 1) * 4;     // 0 or 4
    const float* Ap = X + (size_t)(m0 + lr) * HH + lc;
    const float* Bp = W + (size_t)(n0 + lr) * HH + lc;

    const int tx = tid & 15;          // n-subtile
    const int ty = tid >> 4;          // m-subtile

    u64 acc2[8][4];
#pragma unroll
    for (int i = 0; i < 8; i++)
#pragma unroll
        for (int j = 0; j < 4; j++) acc2[i][j] = 0ull;

    for (int k0 = 0; k0 < HH; k0 += 8) {
        float4 a4 = *(const float4*)(Ap + k0);
        float4 b4 = *(const float4*)(Bp + k0);
        __syncthreads();
        As[lc+0][lr] = a4.x; As[lc+1][lr] = a4.y;
        As[lc+2][lr] = a4.z; As[lc+3][lr] = a4.w;
        Bs[lc+0][lr] = b4.x; Bs[lc+1][lr] = b4.y;
        Bs[lc+2][lr] = b4.z; Bs[lc+3][lr] = b4.w;
        __syncthreads();
#pragma unroll
        for (int kk = 0; kk < 8; kk++) {
            float4 t0 = *(const float4*)&As[kk][ty*8];
            float4 t1 = *(const float4*)&As[kk][ty*8 + 4];
            ulonglong2 bb0 = *(const ulonglong2*)&Bs[kk][tx*8];
            ulonglong2 bb1 = *(const ulonglong2*)&Bs[kk][tx*8 + 4];
            u64 b2v[4];
            b2v[0] = bb0.x; b2v[1] = bb0.y; b2v[2] = bb1.x; b2v[3] = bb1.y;
            u64 a2[8];
            a2[0] = pack2(t0.x, t0.x); a2[1] = pack2(t0.y, t0.y);
            a2[2] = pack2(t0.z, t0.z); a2[3] = pack2(t0.w, t0.w);
            a2[4] = pack2(t1.x, t1.x); a2[5] = pack2(t1.y, t1.y);
            a2[6] = pack2(t1.z, t1.z); a2[7] = pack2(t1.w, t1.w);
#pragma unroll
            for (int i = 0; i < 8; i++)
#pragma unroll
                for (int j = 0; j < 4; j++)
                    fma2(acc2[i][j], a2[i], b2v[j]);
        }
    }

#pragma unroll
    for (int i = 0; i < 8; i++) {
        const int m = m0 + ty*8 + i;
        float* outp = XG + (size_t)m * G4 + n0 + tx*8;
#pragma unroll
        for (int j = 0; j < 4; j++) {
            const int n = n0 + tx*8 + 2*j;
            float v0, v1;
            unpack2(acc2[i][j], v0, v1);
            outp[2*j]   = v0 + b1[n]   + b2[n];
            outp[2*j+1] = v1 + b1[n+1] + b2[n+1];
        }
    }
}

// ---------------------------------------------------------------------------
// One LSTM timestep, v2. Grid = 128 CTAs; CTA `jb` owns hidden columns
// j = jb*8 .. jb*8+7 (32 gate cols: g*8+jj). 256 threads = 2 K-slices x 128.
// Thread tile: 8 batch (4 f32x2 pairs) x 2 gate cols over K/2.
// h staged transposed [k][b] in XOR-swizzled float4 rows; w staged [k][gc].
// K-slices reduced in smem, then fused pointwise gate update.
// ---------------------------------------------------------------------------
__global__ __launch_bounds__(256)
void lstm_step_kernel(const float* __restrict__ xg_t,   // (B, 4H)
                      const float* __restrict__ w_hh,   // (4H, H)
                      const float* __restrict__ h_in,   // (B, H)
                      float* __restrict__ h_out,        // (B, H)
                      float* __restrict__ c,            // (B, H)
                      const float* __restrict__ res_t,  // (B, H)
                      float* __restrict__ out_t)        // (B, H)
{
    const int jb  = blockIdx.x;        // 0..127
    const int tid = threadIdx.x;
    const int ks  = tid >> 7;          // K-slice 0/1
    const int r   = tid & 127;
    const int cg  = r >> 3;            // 0..15 -> cols col0, col0+1
    const int bg  = r & 7;             // 0..7  -> batch b0..b0+7
    const int col0 = cg * 2;
    const int b0   = bg * 8;

    __shared__ float4 hs4[64][16];     // [k][b/4], XOR-swizzled columns
    __shared__ float  ws[64 * 33];     // [k][gate-col], stride 33
    __shared__ float  gs[64 * 33];     // gates [b][gate-col], stride 33

    u64 acc[4][2];
#pragma unroll
    for (int p = 0; p < 4; p++) { acc[p][0] = 0ull; acc[p][1] = 0ull; }

    // loader mappings
    const int lb  = tid >> 2;          // 0..63 (batch row)
    const int lkq = tid & 3;           // 0..3  (k quarter)
    const int wgc = tid >> 3;          // 0..31 (gate col)
    const int wkq = tid & 7;           // 0..7  (k chunk)
    const size_t wrow = (size_t)((wgc >> 3) * HH + jb * 8 + (wgc & 7)) * HH;
    const int q4 = lb >> 2;
    const int e  = lb & 3;

    for (int k0 = 0; k0 < HH; k0 += 64) {
        __syncthreads();
        // stage h: transpose [b][k] -> hs4[k][b/4] with per-4k XOR swizzle
#pragma unroll
        for (int ii = 0; ii < 4; ii++) {
            const int kbase = lkq * 16 + ii * 4;
            float4 v = *(const float4*)(h_in + (size_t)lb * HH + k0 + kbase);
            const int sw = q4 ^ ((kbase >> 2) & 15);
            ((float*)&hs4[kbase + 0][sw])[e] = v.x;
            ((float*)&hs4[kbase + 1][sw])[e] = v.y;
            ((float*)&hs4[kbase + 2][sw])[e] = v.z;
            ((float*)&hs4[kbase + 3][sw])[e] = v.w;
        }
        // stage w: [gc][k] rows -> ws[k][gc]
#pragma unroll
        for (int ii = 0; ii < 2; ii++) {
            const int kb = wkq * 8 + ii * 4;
            float4 wv = *(const float4*)(w_hh + wrow + k0 + kb);
            ws[(kb + 0) * 33 + wgc] = wv.x;
            ws[(kb + 1) * 33 + wgc] = wv.y;
            ws[(kb + 2) * 33 + wgc] = wv.z;
            ws[(kb + 3) * 33 + wgc] = wv.w;
        }
        __syncthreads();

        const int kkbase = ks * 32;
#pragma unroll
        for (int kk2 = 0; kk2 < 32; kk2++) {
            const int kk = kkbase + kk2;
            const int s  = (kk >> 2) & 15;
            ulonglong2 hA = *(const ulonglong2*)&hs4[kk][(2*bg)     ^ s];
            ulonglong2 hB = *(const ulonglong2*)&hs4[kk][(2*bg + 1) ^ s];
            const float w0 = ws[kk * 33 + col0];
            const float w1 = ws[kk * 33 + col0 + 1];
            const u64 w20 = pack2(w0, w0);
            const u64 w21 = pack2(w1, w1);
            fma2(acc[0][0], hA.x, w20); fma2(acc[1][0], hA.y, w20);
            fma2(acc[2][0], hB.x, w20); fma2(acc[3][0], hB.y, w20);
            fma2(acc[0][1], hA.x, w21); fma2(acc[1][1], hA.y, w21);
            fma2(acc[2][1], hB.x, w21); fma2(acc[3][1], hB.y, w21);
        }
    }

    // reduce the two K-slices into gs
    __syncthreads();
    if (ks == 0) {
#pragma unroll
        for (int p = 0; p < 4; p++) {
            float l0, h0v, l1, h1v;
            unpack2(acc[p][0], l0, h0v);
            unpack2(acc[p][1], l1, h1v);
            gs[(b0 + 2*p)     * 33 + col0]     = l0;
            gs[(b0 + 2*p + 1) * 33 + col0]     = h0v;
            gs[(b0 + 2*p)     * 33 + col0 + 1] = l1;
            gs[(b0 + 2*p + 1) * 33 + col0 + 1] = h1v;
        }
    }
    __syncthreads();
    if (ks == 1) {
#pragma unroll
        for (int p = 0; p < 4; p++) {
            float l0, h0v, l1, h1v;
            unpack2(acc[p][0], l0, h0v);
            unpack2(acc[p][1], l1, h1v);
            gs[(b0 + 2*p)     * 33 + col0]     += l0;
            gs[(b0 + 2*p + 1) * 33 + col0]     += h0v;
            gs[(b0 + 2*p)     * 33 + col0 + 1] += l1;
            gs[(b0 + 2*p + 1) * 33 + col0 + 1] += h1v;
        }
    }
    __syncthreads();

    // fused pointwise: 512 (b, jj) pairs, 2 per thread
#pragma unroll
    for (int p = tid; p < 512; p += 256) {
        const int b  = p >> 3;
        const int jj = p & 7;
        const int j  = jb * 8 + jj;
        const size_t idx = (size_t)b * HH + j;
        const size_t xgb = (size_t)b * G4 + j;

        float i_ = gs[b * 33 +      jj] + xg_t[xgb];
        float f_ = gs[b * 33 +  8 + jj] + xg_t[xgb + HH];
        float g_ = gs[b * 33 + 16 + jj] + xg_t[xgb + 2*HH];
        float o_ = gs[b * 33 + 24 + jj] + xg_t[xgb + 3*HH];

        i_ = 1.f / (1.f + __expf(-i_));
        f_ = 1.f / (1.f + __expf(-f_));
        g_ = tanhf(g_);
        o_ = 1.f / (1.f + __expf(-o_));

        const float cv = f_ * c[idx] + i_ * g_;
        c[idx] = cv;
        const float hv = o_ * tanhf(cv);
        h_out[idx] = hv;
        out_t[idx] = hv + res_t[idx];
    }
}

// ---------------------------------------------------------------------------
// Host launch
// ---------------------------------------------------------------------------
extern "C" void kernel_launch(void* const* d_in, const int* in_sizes, int n_in,
                              void* d_out, int out_size)
{
    (void)in_sizes; (void)n_in; (void)out_size;
    const float* x     = (const float*)d_in[0];
    const float* w_ih5 = (const float*)d_in[1];
    const float* w_hh5 = (const float*)d_in[2];
    const float* b_ih5 = (const float*)d_in[3];
    const float* b_hh5 = (const float*)d_in[4];
    const float* w_ih6 = (const float*)d_in[5];
    const float* w_hh6 = (const float*)d_in[6];
    const float* b_ih6 = (const float*)d_in[7];
    const float* b_hh6 = (const float*)d_in[8];
    float* out = (float*)d_out;

    float *xg, *out5, *hbuf, *cbuf;
    cudaGetSymbolAddress((void**)&xg,   g_xg);
    cudaGetSymbolAddress((void**)&out5, g_out5);
    cudaGetSymbolAddress((void**)&hbuf, g_h);
    cudaGetSymbolAddress((void**)&cbuf, g_c);
    float* h0 = hbuf;
    float* h1 = hbuf + BB * HH;

    const dim3 gemm_grid(G4 / 128, MM / 128);   // (32, 128)

    // ---- Layer 5 ----
    init_state_kernel<<<(BB*HH + 1023)/1024, 1024>>>();
    gemm_xg_kernel<<<gemm_grid, 256>>>(x, w_ih5, b_ih5, b_hh5, xg);
    for (int t = 0; t < TT; t++) {
        const float* hin  = (t & 1) ? h1 : h0;
        float*       hout = (t & 1) ? h0 : h1;
        lstm_step_kernel<<<128, 256>>>(
            xg + (size_t)t * BB * G4, w_hh5, hin, hout, cbuf,
            x + (size_t)t * BB * HH, out5 + (size_t)t * BB * HH);
    }

    // ---- Layer 6 ----
    init_state_kernel<<<(BB*HH + 1023)/1024, 1024>>>();
    gemm_xg_kernel<<<gemm_grid, 256>>>(out5, w_ih6, b_ih6, b_hh6, xg);
    for (int t = 0; t < TT; t++) {
        const float* hin  = (t & 1) ? h1 : h0;
        float*       hout = (t & 1) ? h0 : h1;
        lstm_step_kernel<<<128, 256>>>(
            xg + (size_t)t * BB * G4, w_hh6, hin, hout, cbuf,
            out5 + (size_t)t * BB * HH, out + (size_t)t * BB * HH);
    }
}

// round 4
// speedup vs baseline: 1.5220x; 1.5220x over previous
#include <cuda_runtime.h>
#include <cuda_bf16.h>
#include <math.h>
#include <stdint.h>

#define TT 256
#define BB 64
#define HH 1024
#define G4 4096
#define MM (TT*BB)

// ---------------------------------------------------------------------------
// Scratch (device globals: allocation-free per harness rules)
// ---------------------------------------------------------------------------
__device__ float g_xg[(size_t)MM * G4];       // (T,B,4H) precomputed input gates
__device__ float g_out5[(size_t)MM * HH];     // layer-5 output (incl. residual)
__device__ float g_h[2][BB * HH];             // ping-pong hidden state
__device__ float g_c[BB * HH];                // cell state
__device__ __nv_bfloat16 g_ahi[(size_t)MM * HH];   // activation hi split
__device__ __nv_bfloat16 g_alo[(size_t)MM * HH];   // activation lo split
__device__ __nv_bfloat16 g_w5hi[(size_t)G4 * HH];
__device__ __nv_bfloat16 g_w5lo[(size_t)G4 * HH];
__device__ __nv_bfloat16 g_w6hi[(size_t)G4 * HH];
__device__ __nv_bfloat16 g_w6lo[(size_t)G4 * HH];

// ---------------------------------------------------------------------------
// mma.sync helpers (sm_80-class ISA: valid on base sm_103 PTX target)
// ---------------------------------------------------------------------------
__device__ __forceinline__ uint32_t smem_u32(const void* p) {
    uint32_t a;
    asm("{ .reg .u64 t; cvta.to.shared.u64 t, %1; cvt.u32.u64 %0, t; }"
        : "=r"(a) : "l"(p));
    return a;
}
__device__ __forceinline__ void ldsm4(uint32_t* r, uint32_t addr) {
    asm volatile("ldmatrix.sync.aligned.m8n8.x4.shared.b16 {%0,%1,%2,%3}, [%4];"
                 : "=r"(r[0]), "=r"(r[1]), "=r"(r[2]), "=r"(r[3]) : "r"(addr));
}
__device__ __forceinline__ void mma16816(float* d, const uint32_t* a,
                                         const uint32_t* b) {
    asm volatile(
        "mma.sync.aligned.m16n8k16.row.col.f32.bf16.bf16.f32 "
        "{%0,%1,%2,%3}, {%4,%5,%6,%7}, {%8,%9}, {%0,%1,%2,%3};"
        : "+f"(d[0]), "+f"(d[1]), "+f"(d[2]), "+f"(d[3])
        : "r"(a[0]), "r"(a[1]), "r"(a[2]), "r"(a[3]), "r"(b[0]), "r"(b[1]));
}

// ---------------------------------------------------------------------------
// hi/lo bf16 split:  x = hi + lo (exact residual)
// ---------------------------------------------------------------------------
__global__ void split_kernel(const float* __restrict__ in,
                             __nv_bfloat16* __restrict__ hi,
                             __nv_bfloat16* __restrict__ lo, int n) {
    int i = blockIdx.x * blockDim.x + threadIdx.x;
    int stride = gridDim.x * blockDim.x;
    for (; i < n; i += stride) {
        float v = in[i];
        __nv_bfloat16 h = __float2bfloat16(v);
        float r = v - __bfloat162float(h);
        hi[i] = h;
        lo[i] = __float2bfloat16(r);
    }
}

__global__ void init_state_kernel() {
    int i = blockIdx.x * blockDim.x + threadIdx.x;
    if (i < BB * HH) {
        g_h[0][i] = 0.f;
        g_h[1][i] = 0.f;
        g_c[i]    = 0.f;
    }
}

// ---------------------------------------------------------------------------
// Tensor-core input GEMM: XG[m][n] = sum_k X[m][k] W[n][k] + b1[n] + b2[n]
// hi/lo split -> 3 passes accumulated: Ahi*Bhi + Alo*Bhi + Ahi*Blo.
// CTA 128x128, K-chunk 32, double-buffered smem (pad-40 rows, conflict-free
// ldmatrix). Warp tile 32(m) x 64(n): 2 m-frags x 8 n-frags.
// ---------------------------------------------------------------------------
#define PAD 40
#define NCH 96   // 3 passes * (1024/32)

__global__ __launch_bounds__(256)
void gemm_mma_kernel(const __nv_bfloat16* __restrict__ Ahi,
                     const __nv_bfloat16* __restrict__ Alo,
                     const __nv_bfloat16* __restrict__ Bhi,
                     const __nv_bfloat16* __restrict__ Blo,
                     const float* __restrict__ b1,
                     const float* __restrict__ b2,
                     float* __restrict__ XG) {
    __shared__ __nv_bfloat16 As[2][128 * PAD];
    __shared__ __nv_bfloat16 Bs[2][128 * PAD];

    const int tid  = threadIdx.x;
    const int wid  = tid >> 5;
    const int lane = tid & 31;
    const int m0 = blockIdx.y * 128;
    const int n0 = blockIdx.x * 128;
    const int wm = (wid & 3) * 32;    // warp m offset
    const int wn = (wid >> 2) * 64;   // warp n offset

    float acc[2][8][4];
#pragma unroll
    for (int i = 0; i < 2; i++)
#pragma unroll
        for (int j = 0; j < 8; j++)
#pragma unroll
            for (int q = 0; q < 4; q++) acc[i][j][q] = 0.f;

    // staging: thread t loads 32B (2 x uint4) of one row: row=t>>1, koff=(t&1)*16
    const int srow  = tid >> 1;
    const int skoff = (tid & 1) * 16;

    const uint32_t as_base = smem_u32(As);
    const uint32_t bs_base = smem_u32(Bs);

    // ldmatrix lane addressing
    const int a_r = lane & 15;                          // + wm + fm*16
    const int a_c = (lane >> 4) * 8;                    // + kk*16
    const int b_r = ((lane >> 4) * 8) + (lane & 7);     // + wn + fp*16
    const int b_c = ((lane >> 3) & 1) * 8;              // + kk*16

    // prologue: stage chunk 0 (pass 0 = hi*hi, k0 = 0)
    {
        const uint4* a4 = (const uint4*)(Ahi + (size_t)(m0 + srow) * HH + skoff);
        const uint4* b4 = (const uint4*)(Bhi + (size_t)(n0 + srow) * HH + skoff);
        uint4 av0 = a4[0], av1 = a4[1];
        uint4 bv0 = b4[0], bv1 = b4[1];
        *(uint4*)&As[0][srow * PAD + skoff]     = av0;
        *(uint4*)&As[0][srow * PAD + skoff + 8] = av1;
        *(uint4*)&Bs[0][srow * PAD + skoff]     = bv0;
        *(uint4*)&Bs[0][srow * PAD + skoff + 8] = bv1;
    }
    __syncthreads();

    for (int c = 0; c < NCH; c++) {
        const int buf = c & 1;

        // prefetch next chunk to regs
        uint4 av0, av1, bv0, bv1;
        if (c + 1 < NCH) {
            const int cn  = c + 1;
            const int ph  = cn >> 5;
            const int kk0 = (cn & 31) * 32;
            const __nv_bfloat16* Ap = (ph == 1 ? Alo : Ahi);
            const __nv_bfloat16* Bp = (ph == 2 ? Blo : Bhi);
            const uint4* a4 = (const uint4*)(Ap + (size_t)(m0 + srow) * HH + kk0 + skoff);
            const uint4* b4 = (const uint4*)(Bp + (size_t)(n0 + srow) * HH + kk0 + skoff);
            av0 = a4[0]; av1 = a4[1];
            bv0 = b4[0]; bv1 = b4[1];
        }

        // compute on buf: 2 k16-steps
#pragma unroll
        for (int kk = 0; kk < 2; kk++) {
            uint32_t afrag[2][4];
#pragma unroll
            for (int fm = 0; fm < 2; fm++) {
                const int row = wm + fm * 16 + a_r;
                const int col = kk * 16 + a_c;
                ldsm4(afrag[fm], as_base + (buf * 128 * PAD + row * PAD + col) * 2);
            }
            uint32_t bfrag[8][2];
#pragma unroll
            for (int fp = 0; fp < 4; fp++) {
                uint32_t r[4];
                const int row = wn + fp * 16 + b_r;
                const int col = kk * 16 + b_c;
                ldsm4(r, bs_base + (buf * 128 * PAD + row * PAD + col) * 2);
                bfrag[fp * 2][0]     = r[0];
                bfrag[fp * 2][1]     = r[1];
                bfrag[fp * 2 + 1][0] = r[2];
                bfrag[fp * 2 + 1][1] = r[3];
            }
#pragma unroll
            for (int fm = 0; fm < 2; fm++)
#pragma unroll
                for (int fn = 0; fn < 8; fn++)
                    mma16816(acc[fm][fn], afrag[fm], bfrag[fn]);
        }

        // store prefetched chunk to the other buffer
        if (c + 1 < NCH) {
            const int nb = buf ^ 1;
            *(uint4*)&As[nb][srow * PAD + skoff]     = av0;
            *(uint4*)&As[nb][srow * PAD + skoff + 8] = av1;
            *(uint4*)&Bs[nb][srow * PAD + skoff]     = bv0;
            *(uint4*)&Bs[nb][srow * PAD + skoff + 8] = bv1;
        }
        __syncthreads();
    }

    // epilogue: write acc + biases
    const int er = lane >> 2;
    const int ec = (lane & 3) * 2;
#pragma unroll
    for (int fm = 0; fm < 2; fm++) {
#pragma unroll
        for (int fn = 0; fn < 8; fn++) {
            const int row = m0 + wm + fm * 16 + er;
            const int col = n0 + wn + fn * 8 + ec;
            const float bs0 = b1[col] + b2[col];
            const float bs1 = b1[col + 1] + b2[col + 1];
            float* p0 = XG + (size_t)row * G4 + col;
            float* p1 = XG + (size_t)(row + 8) * G4 + col;
            p0[0] = acc[fm][fn][0] + bs0;
            p0[1] = acc[fm][fn][1] + bs1;
            p1[0] = acc[fm][fn][2] + bs0;
            p1[1] = acc[fm][fn][3] + bs1;
        }
    }
}

// ---------------------------------------------------------------------------
// One LSTM timestep (R1-proven inner loop + 2-way K-split, 512 threads).
// Grid = 128 CTAs; CTA jb owns h-cols j = jb*8..jb*8+7 (32 gate cols).
// ---------------------------------------------------------------------------
__global__ __launch_bounds__(512)
void lstm_step_kernel(const float* __restrict__ xg_t,   // (B, 4H)
                      const float* __restrict__ w_hh,   // (4H, H)
                      const float* __restrict__ h_in,   // (B, H)
                      float* __restrict__ h_out,        // (B, H)
                      float* __restrict__ c,            // (B, H)
                      const float* __restrict__ res_t,  // (B, H)
                      float* __restrict__ out_t)        // (B, H)
{
    const int jb  = blockIdx.x;
    const int tid = threadIdx.x;
    const int ks  = tid >> 8;          // K-half 0/1
    const int r   = tid & 255;

    __shared__ float hs[2][32][68];    // [half][k][b] padded
    __shared__ float ws[2][32][33];    // [half][k][gate-col]
    __shared__ float gs[64][33];       // gates [b][gate-col]

    const int col = r & 31;
    const int b0  = (r >> 5) * 8;

    float acc[8];
#pragma unroll
    for (int i = 0; i < 8; i++) acc[i] = 0.f;

    const int hr = r >> 2;             // batch row 0..63
    const int hc = (r & 3) * 8;        // k offset 0,8,16,24
    const int wr = r >> 3;             // gate col 0..31
    const int wc = (r & 7) * 4;        // k offset
    const size_t wrow = (size_t)((wr >> 3) * HH + jb * 8 + (wr & 7)) * HH;

    for (int it = 0; it < 16; it++) {
        const int k0 = ks * 512 + it * 32;
        __syncthreads();
        float4 v0 = *(const float4*)(h_in + (size_t)hr * HH + k0 + hc);
        float4 v1 = *(const float4*)(h_in + (size_t)hr * HH + k0 + hc + 4);
        hs[ks][hc+0][hr] = v0.x; hs[ks][hc+1][hr] = v0.y;
        hs[ks][hc+2][hr] = v0.z; hs[ks][hc+3][hr] = v0.w;
        hs[ks][hc+4][hr] = v1.x; hs[ks][hc+5][hr] = v1.y;
        hs[ks][hc+6][hr] = v1.z; hs[ks][hc+7][hr] = v1.w;
        float4 wv = *(const float4*)(w_hh + wrow + k0 + wc);
        ws[ks][wc+0][wr] = wv.x; ws[ks][wc+1][wr] = wv.y;
        ws[ks][wc+2][wr] = wv.z; ws[ks][wc+3][wr] = wv.w;
        __syncthreads();
#pragma unroll
        for (int kk = 0; kk < 32; kk++) {
            const float w = ws[ks][kk][col];
            float4 hA = *(const float4*)&hs[ks][kk][b0];
            float4 hB = *(const float4*)&hs[ks][kk][b0 + 4];
            acc[0] += hA.x * w; acc[1] += hA.y * w;
            acc[2] += hA.z * w; acc[3] += hA.w * w;
            acc[4] += hB.x * w; acc[5] += hB.y * w;
            acc[6] += hB.z * w; acc[7] += hB.w * w;
        }
    }

    __syncthreads();
    if (ks == 0) {
#pragma unroll
        for (int i = 0; i < 8; i++) gs[b0 + i][col] = acc[i];
    }
    __syncthreads();
    if (ks == 1) {
#pragma unroll
        for (int i = 0; i < 8; i++) gs[b0 + i][col] += acc[i];
    }
    __syncthreads();

    {
        const int b  = tid >> 3;
        const int jj = tid & 7;
        const int j  = jb * 8 + jj;
        const size_t idx = (size_t)b * HH + j;
        const size_t xgb = (size_t)b * G4 + j;

        float i_ = gs[b][     jj] + xg_t[xgb];
        float f_ = gs[b][ 8 + jj] + xg_t[xgb + HH];
        float g_ = gs[b][16 + jj] + xg_t[xgb + 2 * HH];
        float o_ = gs[b][24 + jj] + xg_t[xgb + 3 * HH];

        i_ = 1.f / (1.f + __expf(-i_));
        f_ = 1.f / (1.f + __expf(-f_));
        g_ = tanhf(g_);
        o_ = 1.f / (1.f + __expf(-o_));

        const float cv = f_ * c[idx] + i_ * g_;
        c[idx] = cv;
        const float hv = o_ * tanhf(cv);
        h_out[idx] = hv;
        out_t[idx] = hv + res_t[idx];
    }
}

// ---------------------------------------------------------------------------
// Host launch
// ---------------------------------------------------------------------------
extern "C" void kernel_launch(void* const* d_in, const int* in_sizes, int n_in,
                              void* d_out, int out_size)
{
    (void)in_sizes; (void)n_in; (void)out_size;
    const float* x     = (const float*)d_in[0];
    const float* w_ih5 = (const float*)d_in[1];
    const float* w_hh5 = (const float*)d_in[2];
    const float* b_ih5 = (const float*)d_in[3];
    const float* b_hh5 = (const float*)d_in[4];
    const float* w_ih6 = (const float*)d_in[5];
    const float* w_hh6 = (const float*)d_in[6];
    const float* b_ih6 = (const float*)d_in[7];
    const float* b_hh6 = (const float*)d_in[8];
    float* out = (float*)d_out;

    float *xg, *out5, *hbuf, *cbuf;
    __nv_bfloat16 *ahi, *alo, *w5hi, *w5lo, *w6hi, *w6lo;
    cudaGetSymbolAddress((void**)&xg,   g_xg);
    cudaGetSymbolAddress((void**)&out5, g_out5);
    cudaGetSymbolAddress((void**)&hbuf, g_h);
    cudaGetSymbolAddress((void**)&cbuf, g_c);
    cudaGetSymbolAddress((void**)&ahi,  g_ahi);
    cudaGetSymbolAddress((void**)&alo,  g_alo);
    cudaGetSymbolAddress((void**)&w5hi, g_w5hi);
    cudaGetSymbolAddress((void**)&w5lo, g_w5lo);
    cudaGetSymbolAddress((void**)&w6hi, g_w6hi);
    cudaGetSymbolAddress((void**)&w6lo, g_w6lo);
    float* h0 = hbuf;
    float* h1 = hbuf + BB * HH;

    const dim3 gemm_grid(G4 / 128, MM / 128);   // (32, 128)

    // weight splits (once per call; cheap)
    split_kernel<<<4096, 256>>>(w_ih5, w5hi, w5lo, G4 * HH);
    split_kernel<<<4096, 256>>>(w_ih6, w6hi, w6lo, G4 * HH);

    // ---- Layer 5 ----
    split_kernel<<<8192, 256>>>(x, ahi, alo, MM * HH);
    init_state_kernel<<<(BB * HH + 1023) / 1024, 1024>>>();
    gemm_mma_kernel<<<gemm_grid, 256>>>(ahi, alo, w5hi, w5lo, b_ih5, b_hh5, xg);
    for (int t = 0; t < TT; t++) {
        const float* hin  = (t & 1) ? h1 : h0;
        float*       hout = (t & 1) ? h0 : h1;
        lstm_step_kernel<<<128, 512>>>(
            xg + (size_t)t * BB * G4, w_hh5, hin, hout, cbuf,
            x + (size_t)t * BB * HH, out5 + (size_t)t * BB * HH);
    }

    // ---- Layer 6 ----
    split_kernel<<<8192, 256>>>(out5, ahi, alo, MM * HH);
    init_state_kernel<<<(BB * HH + 1023) / 1024, 1024>>>();
    gemm_mma_kernel<<<gemm_grid, 256>>>(ahi, alo, w6hi, w6lo, b_ih6, b_hh6, xg);
    for (int t = 0; t < TT; t++) {
        const float* hin  = (t & 1) ? h1 : h0;
        float*       hout = (t & 1) ? h0 : h1;
        lstm_step_kernel<<<128, 512>>>(
            xg + (size_t)t * BB * G4, w_hh6, hin, hout, cbuf,
            out5 + (size_t)t * BB * HH, out + (size_t)t * BB * HH);
    }
}

// round 5
// speedup vs baseline: 1.8023x; 1.1842x over previous
#include <cuda_runtime.h>
#include <cuda_bf16.h>
#include <math.h>
#include <stdint.h>

#define TT 256
#define BB 64
#define HH 1024
#define G4 4096
#define MM (TT*BB)

// ---------------------------------------------------------------------------
// Scratch (device globals: allocation-free per harness rules)
// ---------------------------------------------------------------------------
__device__ float g_xg[(size_t)MM * G4];       // (T,B,4H) precomputed input gates
__device__ float g_out5[(size_t)MM * HH];     // layer-5 output (incl. residual)
__device__ float g_c[BB * HH];                // cell state
__device__ __nv_bfloat16 g_hhi[2][BB * HH];   // ping-pong hidden hi split
__device__ __nv_bfloat16 g_hlo[2][BB * HH];   // ping-pong hidden lo split
__device__ __nv_bfloat16 g_ahi[(size_t)MM * HH];   // activation hi split
__device__ __nv_bfloat16 g_alo[(size_t)MM * HH];   // activation lo split
__device__ __nv_bfloat16 g_w5hi[(size_t)G4 * HH];  // w_ih5 splits
__device__ __nv_bfloat16 g_w5lo[(size_t)G4 * HH];
__device__ __nv_bfloat16 g_w6hi[(size_t)G4 * HH];
__device__ __nv_bfloat16 g_w6lo[(size_t)G4 * HH];
__device__ __nv_bfloat16 g_u5hi[(size_t)G4 * HH];  // w_hh5 splits
__device__ __nv_bfloat16 g_u5lo[(size_t)G4 * HH];
__device__ __nv_bfloat16 g_u6hi[(size_t)G4 * HH];
__device__ __nv_bfloat16 g_u6lo[(size_t)G4 * HH];

// ---------------------------------------------------------------------------
// mma.sync helpers (sm_80-class ISA: valid on base sm_103 PTX target)
// ---------------------------------------------------------------------------
__device__ __forceinline__ uint32_t smem_u32(const void* p) {
    uint32_t a;
    asm("{ .reg .u64 t; cvta.to.shared.u64 t, %1; cvt.u32.u64 %0, t; }"
        : "=r"(a) : "l"(p));
    return a;
}
__device__ __forceinline__ void ldsm4(uint32_t* r, uint32_t addr) {
    asm volatile("ldmatrix.sync.aligned.m8n8.x4.shared.b16 {%0,%1,%2,%3}, [%4];"
                 : "=r"(r[0]), "=r"(r[1]), "=r"(r[2]), "=r"(r[3]) : "r"(addr));
}
__device__ __forceinline__ void mma16816(float* d, const uint32_t* a,
                                         const uint32_t* b) {
    asm volatile(
        "mma.sync.aligned.m16n8k16.row.col.f32.bf16.bf16.f32 "
        "{%0,%1,%2,%3}, {%4,%5,%6,%7}, {%8,%9}, {%0,%1,%2,%3};"
        : "+f"(d[0]), "+f"(d[1]), "+f"(d[2]), "+f"(d[3])
        : "r"(a[0]), "r"(a[1]), "r"(a[2]), "r"(a[3]), "r"(b[0]), "r"(b[1]));
}

// ---------------------------------------------------------------------------
// hi/lo bf16 split:  x = hi + lo (exact residual)
// ---------------------------------------------------------------------------
__global__ void split_kernel(const float* __restrict__ in,
                             __nv_bfloat16* __restrict__ hi,
                             __nv_bfloat16* __restrict__ lo, int n) {
    int i = blockIdx.x * blockDim.x + threadIdx.x;
    int stride = gridDim.x * blockDim.x;
    for (; i < n; i += stride) {
        float v = in[i];
        __nv_bfloat16 h = __float2bfloat16(v);
        float r = v - __bfloat162float(h);
        hi[i] = h;
        lo[i] = __float2bfloat16(r);
    }
}

__global__ void init_state_kernel() {
    int i = blockIdx.x * blockDim.x + threadIdx.x;
    if (i < BB * HH) {
        g_c[i] = 0.f;
        __nv_bfloat16 z = __float2bfloat16(0.f);
        g_hhi[0][i] = z; g_hhi[1][i] = z;
        g_hlo[0][i] = z; g_hlo[1][i] = z;
    }
}

// ---------------------------------------------------------------------------
// Tensor-core input GEMM (unchanged from R4 — verified).
// XG[m][n] = sum_k X[m][k] W[n][k] + b1[n] + b2[n]; 3-pass hi/lo split.
// ---------------------------------------------------------------------------
#define PAD 40
#define NCH 96

__global__ __launch_bounds__(256)
void gemm_mma_kernel(const __nv_bfloat16* __restrict__ Ahi,
                     const __nv_bfloat16* __restrict__ Alo,
                     const __nv_bfloat16* __restrict__ Bhi,
                     const __nv_bfloat16* __restrict__ Blo,
                     const float* __restrict__ b1,
                     const float* __restrict__ b2,
                     float* __restrict__ XG) {
    __shared__ __nv_bfloat16 As[2][128 * PAD];
    __shared__ __nv_bfloat16 Bs[2][128 * PAD];

    const int tid  = threadIdx.x;
    const int wid  = tid >> 5;
    const int lane = tid & 31;
    const int m0 = blockIdx.y * 128;
    const int n0 = blockIdx.x * 128;
    const int wm = (wid & 3) * 32;
    const int wn = (wid >> 2) * 64;

    float acc[2][8][4];
#pragma unroll
    for (int i = 0; i < 2; i++)
#pragma unroll
        for (int j = 0; j < 8; j++)
#pragma unroll
            for (int q = 0; q < 4; q++) acc[i][j][q] = 0.f;

    const int srow  = tid >> 1;
    const int skoff = (tid & 1) * 16;
    const uint32_t as_base = smem_u32(As);
    const uint32_t bs_base = smem_u32(Bs);

    const int a_r = lane & 15;
    const int a_c = (lane >> 4) * 8;
    const int b_r = ((lane >> 4) * 8) + (lane & 7);
    const int b_c = ((lane >> 3) & 1) * 8;

    {
        const uint4* a4 = (const uint4*)(Ahi + (size_t)(m0 + srow) * HH + skoff);
        const uint4* b4 = (const uint4*)(Bhi + (size_t)(n0 + srow) * HH + skoff);
        uint4 av0 = a4[0], av1 = a4[1];
        uint4 bv0 = b4[0], bv1 = b4[1];
        *(uint4*)&As[0][srow * PAD + skoff]     = av0;
        *(uint4*)&As[0][srow * PAD + skoff + 8] = av1;
        *(uint4*)&Bs[0][srow * PAD + skoff]     = bv0;
        *(uint4*)&Bs[0][srow * PAD + skoff + 8] = bv1;
    }
    __syncthreads();

    for (int c = 0; c < NCH; c++) {
        const int buf = c & 1;
        uint4 av0, av1, bv0, bv1;
        if (c + 1 < NCH) {
            const int cn  = c + 1;
            const int ph  = cn >> 5;
            const int kk0 = (cn & 31) * 32;
            const __nv_bfloat16* Ap = (ph == 1 ? Alo : Ahi);
            const __nv_bfloat16* Bp = (ph == 2 ? Blo : Bhi);
            const uint4* a4 = (const uint4*)(Ap + (size_t)(m0 + srow) * HH + kk0 + skoff);
            const uint4* b4 = (const uint4*)(Bp + (size_t)(n0 + srow) * HH + kk0 + skoff);
            av0 = a4[0]; av1 = a4[1];
            bv0 = b4[0]; bv1 = b4[1];
        }

#pragma unroll
        for (int kk = 0; kk < 2; kk++) {
            uint32_t afrag[2][4];
#pragma unroll
            for (int fm = 0; fm < 2; fm++) {
                const int row = wm + fm * 16 + a_r;
                const int col = kk * 16 + a_c;
                ldsm4(afrag[fm], as_base + (buf * 128 * PAD + row * PAD + col) * 2);
            }
            uint32_t bfrag[8][2];
#pragma unroll
            for (int fp = 0; fp < 4; fp++) {
                uint32_t r[4];
                const int row = wn + fp * 16 + b_r;
                const int col = kk * 16 + b_c;
                ldsm4(r, bs_base + (buf * 128 * PAD + row * PAD + col) * 2);
                bfrag[fp * 2][0]     = r[0];
                bfrag[fp * 2][1]     = r[1];
                bfrag[fp * 2 + 1][0] = r[2];
                bfrag[fp * 2 + 1][1] = r[3];
            }
#pragma unroll
            for (int fm = 0; fm < 2; fm++)
#pragma unroll
                for (int fn = 0; fn < 8; fn++)
                    mma16816(acc[fm][fn], afrag[fm], bfrag[fn]);
        }

        if (c + 1 < NCH) {
            const int nb = buf ^ 1;
            *(uint4*)&As[nb][srow * PAD + skoff]     = av0;
            *(uint4*)&As[nb][srow * PAD + skoff + 8] = av1;
            *(uint4*)&Bs[nb][srow * PAD + skoff]     = bv0;
            *(uint4*)&Bs[nb][srow * PAD + skoff + 8] = bv1;
        }
        __syncthreads();
    }

    const int er = lane >> 2;
    const int ec = (lane & 3) * 2;
#pragma unroll
    for (int fm = 0; fm < 2; fm++) {
#pragma unroll
        for (int fn = 0; fn < 8; fn++) {
            const int row = m0 + wm + fm * 16 + er;
            const int col = n0 + wn + fn * 8 + ec;
            const float bs0 = b1[col] + b2[col];
            const float bs1 = b1[col + 1] + b2[col + 1];
            float* p0 = XG + (size_t)row * G4 + col;
            float* p1 = XG + (size_t)(row + 8) * G4 + col;
            p0[0] = acc[fm][fn][0] + bs0;
            p0[1] = acc[fm][fn][1] + bs1;
            p1[0] = acc[fm][fn][2] + bs0;
            p1[1] = acc[fm][fn][3] + bs1;
        }
    }
}

// ---------------------------------------------------------------------------
// Tensor-core LSTM step. Grid = 64 CTAs x 256 threads.
// CTA jb owns h-cols j = jb*16..jb*16+15 -> 64 gate rows (4 strips of 16:
// local row ln = g*16+jj <-> W row g*1024 + jb*16 + jj).
// gates[64b][64n] = h_hi*Whi + h_lo*Whi + h_hi*Wlo over K=1024 (k-chunk 32,
// double-buffered, R4-verified frag layout). Fused pointwise epilogue emits
// c, out_t and next h as exact bf16 hi/lo split.
// ---------------------------------------------------------------------------
#define TLSZ (64 * PAD)                 // halfwords per tile

__global__ __launch_bounds__(256)
void lstm_step_mma(const float* __restrict__ xg_t,        // (B, 4H)
                   const __nv_bfloat16* __restrict__ Whi, // (4H, H)
                   const __nv_bfloat16* __restrict__ Wlo,
                   const __nv_bfloat16* __restrict__ hhi_in,
                   const __nv_bfloat16* __restrict__ hlo_in,
                   __nv_bfloat16* __restrict__ hhi_out,
                   __nv_bfloat16* __restrict__ hlo_out,
                   float* __restrict__ c,
                   const float* __restrict__ res_t,
                   float* __restrict__ out_t)
{
    // arena: [buf][tile][64*PAD] halfwords; tiles: 0=Ahi 1=Alo 2=Bhi 3=Blo.
    // Overlaid by gates gs[64][65] floats after the mainloop.
    __shared__ __align__(16) __nv_bfloat16 sm[2][4][TLSZ];

    const int tid  = threadIdx.x;
    const int wid  = tid >> 5;
    const int lane = tid & 31;
    const int jb   = blockIdx.x;       // 0..63
    const int wm   = (wid & 3) * 16;   // warp m offset (batch)
    const int wn   = (wid >> 2) * 32;  // warp n offset (gate col)

    float acc[4][4];
#pragma unroll
    for (int i = 0; i < 4; i++)
#pragma unroll
        for (int q = 0; q < 4; q++) acc[i][q] = 0.f;

    // staging: thread -> (row, 8-halfword segment)
    const int srow = tid >> 2;         // 0..63
    const int sseg = (tid & 3) * 8;    // 0,8,16,24
    const size_t a_off = (size_t)srow * HH + sseg;
    const size_t b_off = (size_t)((srow >> 4) * HH + jb * 16 + (srow & 15)) * HH + sseg;

    const uint32_t smb = smem_u32(sm);
    const int a_r = lane & 15;
    const int a_c = (lane >> 4) * 8;
    const int b_r = ((lane >> 4) * 8) + (lane & 7);
    const int b_c = ((lane >> 3) & 1) * 8;

    // prologue: stage chunk 0 into buf 0
    {
        uint4 t0 = *(const uint4*)(hhi_in + a_off);
        uint4 t1 = *(const uint4*)(hlo_in + a_off);
        uint4 t2 = *(const uint4*)(Whi + b_off);
        uint4 t3 = *(const uint4*)(Wlo + b_off);
        *(uint4*)&sm[0][0][srow * PAD + sseg] = t0;
        *(uint4*)&sm[0][1][srow * PAD + sseg] = t1;
        *(uint4*)&sm[0][2][srow * PAD + sseg] = t2;
        *(uint4*)&sm[0][3][srow * PAD + sseg] = t3;
    }
    __syncthreads();

    for (int ch = 0; ch < 32; ch++) {
        const int buf = ch & 1;
        uint4 t0, t1, t2, t3;
        if (ch + 1 < 32) {
            const int k0 = (ch + 1) * 32;
            t0 = *(const uint4*)(hhi_in + a_off + k0);
            t1 = *(const uint4*)(hlo_in + a_off + k0);
            t2 = *(const uint4*)(Whi + b_off + k0);
            t3 = *(const uint4*)(Wlo + b_off + k0);
        }

        const uint32_t base = smb + buf * (4 * TLSZ * 2);
#pragma unroll
        for (int kk = 0; kk < 2; kk++) {
            uint32_t ahi[4], alo[4];
            ldsm4(ahi, base + 0 * (TLSZ * 2) + ((wm + a_r) * PAD + kk * 16 + a_c) * 2);
            ldsm4(alo, base + 1 * (TLSZ * 2) + ((wm + a_r) * PAD + kk * 16 + a_c) * 2);
            uint32_t bhi[4][2], blo[4][2];
#pragma unroll
            for (int fp = 0; fp < 2; fp++) {
                uint32_t r[4];
                const int row = wn + fp * 16 + b_r;
                ldsm4(r, base + 2 * (TLSZ * 2) + (row * PAD + kk * 16 + b_c) * 2);
                bhi[fp*2][0] = r[0]; bhi[fp*2][1] = r[1];
                bhi[fp*2+1][0] = r[2]; bhi[fp*2+1][1] = r[3];
                ldsm4(r, base + 3 * (TLSZ * 2) + (row * PAD + kk * 16 + b_c) * 2);
                blo[fp*2][0] = r[0]; blo[fp*2][1] = r[1];
                blo[fp*2+1][0] = r[2]; blo[fp*2+1][1] = r[3];
            }
#pragma unroll
            for (int fn = 0; fn < 4; fn++) {
                mma16816(acc[fn], ahi, bhi[fn]);
                mma16816(acc[fn], alo, bhi[fn]);
                mma16816(acc[fn], ahi, blo[fn]);
            }
        }

        if (ch + 1 < 32) {
            const int nb = buf ^ 1;
            *(uint4*)&sm[nb][0][srow * PAD + sseg] = t0;
            *(uint4*)&sm[nb][1][srow * PAD + sseg] = t1;
            *(uint4*)&sm[nb][2][srow * PAD + sseg] = t2;
            *(uint4*)&sm[nb][3][srow * PAD + sseg] = t3;
        }
        __syncthreads();
    }

    // gates -> smem overlay (64 x 65 floats = 16.6KB < 40KB arena)
    float* gs = (float*)sm;
    {
        const int er = lane >> 2;
        const int ec = (lane & 3) * 2;
#pragma unroll
        for (int fn = 0; fn < 4; fn++) {
            const int col = wn + fn * 8 + ec;
            gs[(wm + er) * 65 + col]       = acc[fn][0];
            gs[(wm + er) * 65 + col + 1]   = acc[fn][1];
            gs[(wm + er + 8) * 65 + col]   = acc[fn][2];
            gs[(wm + er + 8) * 65 + col+1] = acc[fn][3];
        }
    }
    __syncthreads();

    // fused pointwise: 1024 (b, jj) pairs, 4 per thread
#pragma unroll
    for (int rr = 0; rr < 4; rr++) {
        const int idx = tid + rr * 256;
        const int b  = idx >> 4;
        const int jj = idx & 15;
        const int j  = jb * 16 + jj;
        const size_t ih  = (size_t)b * HH + j;
        const size_t ixg = (size_t)b * G4 + j;

        float i_ = gs[b * 65 +      jj] + xg_t[ixg];
        float f_ = gs[b * 65 + 16 + jj] + xg_t[ixg + HH];
        float g_ = gs[b * 65 + 32 + jj] + xg_t[ixg + 2 * HH];
        float o_ = gs[b * 65 + 48 + jj] + xg_t[ixg + 3 * HH];

        i_ = 1.f / (1.f + __expf(-i_));
        f_ = 1.f / (1.f + __expf(-f_));
        g_ = tanhf(g_);
        o_ = 1.f / (1.f + __expf(-o_));

        const float cv = f_ * c[ih] + i_ * g_;
        c[ih] = cv;
        const float hv = o_ * tanhf(cv);
        __nv_bfloat16 hh = __float2bfloat16(hv);
        hhi_out[ih] = hh;
        hlo_out[ih] = __float2bfloat16(hv - __bfloat162float(hh));
        out_t[ih] = hv + res_t[ih];
    }
}

// ---------------------------------------------------------------------------
// Host launch
// ---------------------------------------------------------------------------
extern "C" void kernel_launch(void* const* d_in, const int* in_sizes, int n_in,
                              void* d_out, int out_size)
{
    (void)in_sizes; (void)n_in; (void)out_size;
    const float* x     = (const float*)d_in[0];
    const float* w_ih5 = (const float*)d_in[1];
    const float* w_hh5 = (const float*)d_in[2];
    const float* b_ih5 = (const float*)d_in[3];
    const float* b_hh5 = (const float*)d_in[4];
    const float* w_ih6 = (const float*)d_in[5];
    const float* w_hh6 = (const float*)d_in[6];
    const float* b_ih6 = (const float*)d_in[7];
    const float* b_hh6 = (const float*)d_in[8];
    float* out = (float*)d_out;

    float *xg, *out5, *cbuf;
    __nv_bfloat16 *ahi, *alo, *w5hi, *w5lo, *w6hi, *w6lo;
    __nv_bfloat16 *u5hi, *u5lo, *u6hi, *u6lo, *hhi, *hlo;
    cudaGetSymbolAddress((void**)&xg,   g_xg);
    cudaGetSymbolAddress((void**)&out5, g_out5);
    cudaGetSymbolAddress((void**)&cbuf, g_c);
    cudaGetSymbolAddress((void**)&ahi,  g_ahi);
    cudaGetSymbolAddress((void**)&alo,  g_alo);
    cudaGetSymbolAddress((void**)&w5hi, g_w5hi);
    cudaGetSymbolAddress((void**)&w5lo, g_w5lo);
    cudaGetSymbolAddress((void**)&w6hi, g_w6hi);
    cudaGetSymbolAddress((void**)&w6lo, g_w6lo);
    cudaGetSymbolAddress((void**)&u5hi, g_u5hi);
    cudaGetSymbolAddress((void**)&u5lo, g_u5lo);
    cudaGetSymbolAddress((void**)&u6hi, g_u6hi);
    cudaGetSymbolAddress((void**)&u6lo, g_u6lo);
    cudaGetSymbolAddress((void**)&hhi,  g_hhi);
    cudaGetSymbolAddress((void**)&hlo,  g_hlo);

    const dim3 gemm_grid(G4 / 128, MM / 128);   // (32, 128)

    // weight splits
    split_kernel<<<4096, 256>>>(w_ih5, w5hi, w5lo, G4 * HH);
    split_kernel<<<4096, 256>>>(w_ih6, w6hi, w6lo, G4 * HH);
    split_kernel<<<4096, 256>>>(w_hh5, u5hi, u5lo, G4 * HH);
    split_kernel<<<4096, 256>>>(w_hh6, u6hi, u6lo, G4 * HH);

    // ---- Layer 5 ----
    split_kernel<<<8192, 256>>>(x, ahi, alo, MM * HH);
    init_state_kernel<<<(BB * HH + 1023) / 1024, 1024>>>();
    gemm_mma_kernel<<<gemm_grid, 256>>>(ahi, alo, w5hi, w5lo, b_ih5, b_hh5, xg);
    for (int t = 0; t < TT; t++) {
        const int p = t & 1;
        lstm_step_mma<<<64, 256>>>(
            xg + (size_t)t * BB * G4, u5hi, u5lo,
            hhi + p * BB * HH, hlo + p * BB * HH,
            hhi + (1 - p) * BB * HH, hlo + (1 - p) * BB * HH,
            cbuf, x + (size_t)t * BB * HH, out5 + (size_t)t * BB * HH);
    }

    // ---- Layer 6 ----
    split_kernel<<<8192, 256>>>(out5, ahi, alo, MM * HH);
    init_state_kernel<<<(BB * HH + 1023) / 1024, 1024>>>();
    gemm_mma_kernel<<<gemm_grid, 256>>>(ahi, alo, w6hi, w6lo, b_ih6, b_hh6, xg);
    for (int t = 0; t < TT; t++) {
        const int p = t & 1;
        lstm_step_mma<<<64, 256>>>(
            xg + (size_t)t * BB * G4, u6hi, u6lo,
            hhi + p * BB * HH, hlo + p * BB * HH,
            hhi + (1 - p) * BB * HH, hlo + (1 - p) * BB * HH,
            cbuf, out5 + (size_t)t * BB * HH, out + (size_t)t * BB * HH);
    }
}

// round 6
// speedup vs baseline: 2.8360x; 1.5735x over previous
#include <cuda_runtime.h>
#include <cuda_bf16.h>
#include <math.h>
#include <stdint.h>

#define TT 256
#define BB 64
#define HH 1024
#define G4 4096
#define MM (TT*BB)
#define NCT 128           // CTAs in persistent step kernel

// ---------------------------------------------------------------------------
// Scratch (device globals: allocation-free per harness rules)
// ---------------------------------------------------------------------------
__device__ float g_xg[(size_t)MM * G4];
__device__ float g_out5[(size_t)MM * HH];
__device__ __nv_bfloat16 g_hhi[2][BB * HH];
__device__ __nv_bfloat16 g_hlo[2][BB * HH];
__device__ __nv_bfloat16 g_ahi[(size_t)MM * HH];
__device__ __nv_bfloat16 g_alo[(size_t)MM * HH];
__device__ __nv_bfloat16 g_w5hi[(size_t)G4 * HH];
__device__ __nv_bfloat16 g_w5lo[(size_t)G4 * HH];
__device__ __nv_bfloat16 g_w6hi[(size_t)G4 * HH];
__device__ __nv_bfloat16 g_w6lo[(size_t)G4 * HH];
__device__ __nv_bfloat16 g_u5hi[(size_t)G4 * HH];
__device__ __nv_bfloat16 g_u5lo[(size_t)G4 * HH];
__device__ __nv_bfloat16 g_u6hi[(size_t)G4 * HH];
__device__ __nv_bfloat16 g_u6lo[(size_t)G4 * HH];
__device__ int g_ctr[2 * TT];                 // per-layer, per-step barrier counters

// ---------------------------------------------------------------------------
// mma.sync helpers
// ---------------------------------------------------------------------------
__device__ __forceinline__ uint32_t smem_u32(const void* p) {
    uint32_t a;
    asm("{ .reg .u64 t; cvta.to.shared.u64 t, %1; cvt.u32.u64 %0, t; }"
        : "=r"(a) : "l"(p));
    return a;
}
__device__ __forceinline__ void ldsm4(uint32_t* r, uint32_t addr) {
    asm volatile("ldmatrix.sync.aligned.m8n8.x4.shared.b16 {%0,%1,%2,%3}, [%4];"
                 : "=r"(r[0]), "=r"(r[1]), "=r"(r[2]), "=r"(r[3]) : "r"(addr));
}
__device__ __forceinline__ void mma16816(float* d, const uint32_t* a,
                                         const uint32_t* b) {
    asm volatile(
        "mma.sync.aligned.m16n8k16.row.col.f32.bf16.bf16.f32 "
        "{%0,%1,%2,%3}, {%4,%5,%6,%7}, {%8,%9}, {%0,%1,%2,%3};"
        : "+f"(d[0]), "+f"(d[1]), "+f"(d[2]), "+f"(d[3])
        : "r"(a[0]), "r"(a[1]), "r"(a[2]), "r"(a[3]), "r"(b[0]), "r"(b[1]));
}

// ---------------------------------------------------------------------------
// hi/lo bf16 split
// ---------------------------------------------------------------------------
__global__ void split_kernel(const float* __restrict__ in,
                             __nv_bfloat16* __restrict__ hi,
                             __nv_bfloat16* __restrict__ lo, int n) {
    int i = blockIdx.x * blockDim.x + threadIdx.x;
    int stride = gridDim.x * blockDim.x;
    for (; i < n; i += stride) {
        float v = in[i];
        __nv_bfloat16 h = __float2bfloat16(v);
        float r = v - __bfloat162float(h);
        hi[i] = h;
        lo[i] = __float2bfloat16(r);
    }
}

__global__ void init_state_kernel() {
    int i = blockIdx.x * blockDim.x + threadIdx.x;
    if (i < BB * HH) {
        __nv_bfloat16 z = __float2bfloat16(0.f);
        g_hhi[0][i] = z; g_hhi[1][i] = z;
        g_hlo[0][i] = z; g_hlo[1][i] = z;
    }
    if (i < 2 * TT) g_ctr[i] = 0;
}

// ---------------------------------------------------------------------------
// Tensor-core input GEMM (R4/R5-verified, unchanged).
// ---------------------------------------------------------------------------
#define PAD 40
#define NCH 96

__global__ __launch_bounds__(256)
void gemm_mma_kernel(const __nv_bfloat16* __restrict__ Ahi,
                     const __nv_bfloat16* __restrict__ Alo,
                     const __nv_bfloat16* __restrict__ Bhi,
                     const __nv_bfloat16* __restrict__ Blo,
                     const float* __restrict__ b1,
                     const float* __restrict__ b2,
                     float* __restrict__ XG) {
    __shared__ __nv_bfloat16 As[2][128 * PAD];
    __shared__ __nv_bfloat16 Bs[2][128 * PAD];

    const int tid  = threadIdx.x;
    const int wid  = tid >> 5;
    const int lane = tid & 31;
    const int m0 = blockIdx.y * 128;
    const int n0 = blockIdx.x * 128;
    const int wm = (wid & 3) * 32;
    const int wn = (wid >> 2) * 64;

    float acc[2][8][4];
#pragma unroll
    for (int i = 0; i < 2; i++)
#pragma unroll
        for (int j = 0; j < 8; j++)
#pragma unroll
            for (int q = 0; q < 4; q++) acc[i][j][q] = 0.f;

    const int srow  = tid >> 1;
    const int skoff = (tid & 1) * 16;
    const uint32_t as_base = smem_u32(As);
    const uint32_t bs_base = smem_u32(Bs);

    const int a_r = lane & 15;
    const int a_c = (lane >> 4) * 8;
    const int b_r = ((lane >> 4) * 8) + (lane & 7);
    const int b_c = ((lane >> 3) & 1) * 8;

    {
        const uint4* a4 = (const uint4*)(Ahi + (size_t)(m0 + srow) * HH + skoff);
        const uint4* b4 = (const uint4*)(Bhi + (size_t)(n0 + srow) * HH + skoff);
        uint4 av0 = a4[0], av1 = a4[1];
        uint4 bv0 = b4[0], bv1 = b4[1];
        *(uint4*)&As[0][srow * PAD + skoff]     = av0;
        *(uint4*)&As[0][srow * PAD + skoff + 8] = av1;
        *(uint4*)&Bs[0][srow * PAD + skoff]     = bv0;
        *(uint4*)&Bs[0][srow * PAD + skoff + 8] = bv1;
    }
    __syncthreads();

    for (int c = 0; c < NCH; c++) {
        const int buf = c & 1;
        uint4 av0, av1, bv0, bv1;
        if (c + 1 < NCH) {
            const int cn  = c + 1;
            const int ph  = cn >> 5;
            const int kk0 = (cn & 31) * 32;
            const __nv_bfloat16* Ap = (ph == 1 ? Alo : Ahi);
            const __nv_bfloat16* Bp = (ph == 2 ? Blo : Bhi);
            const uint4* a4 = (const uint4*)(Ap + (size_t)(m0 + srow) * HH + kk0 + skoff);
            const uint4* b4 = (const uint4*)(Bp + (size_t)(n0 + srow) * HH + kk0 + skoff);
            av0 = a4[0]; av1 = a4[1];
            bv0 = b4[0]; bv1 = b4[1];
        }

#pragma unroll
        for (int kk = 0; kk < 2; kk++) {
            uint32_t afrag[2][4];
#pragma unroll
            for (int fm = 0; fm < 2; fm++) {
                const int row = wm + fm * 16 + a_r;
                const int col = kk * 16 + a_c;
                ldsm4(afrag[fm], as_base + (buf * 128 * PAD + row * PAD + col) * 2);
            }
            uint32_t bfrag[8][2];
#pragma unroll
            for (int fp = 0; fp < 4; fp++) {
                uint32_t r[4];
                const int row = wn + fp * 16 + b_r;
                const int col = kk * 16 + b_c;
                ldsm4(r, bs_base + (buf * 128 * PAD + row * PAD + col) * 2);
                bfrag[fp * 2][0]     = r[0];
                bfrag[fp * 2][1]     = r[1];
                bfrag[fp * 2 + 1][0] = r[2];
                bfrag[fp * 2 + 1][1] = r[3];
            }
#pragma unroll
            for (int fm = 0; fm < 2; fm++)
#pragma unroll
                for (int fn = 0; fn < 8; fn++)
                    mma16816(acc[fm][fn], afrag[fm], bfrag[fn]);
        }

        if (c + 1 < NCH) {
            const int nb = buf ^ 1;
            *(uint4*)&As[nb][srow * PAD + skoff]     = av0;
            *(uint4*)&As[nb][srow * PAD + skoff + 8] = av1;
            *(uint4*)&Bs[nb][srow * PAD + skoff]     = bv0;
            *(uint4*)&Bs[nb][srow * PAD + skoff + 8] = bv1;
        }
        __syncthreads();
    }

    const int er = lane >> 2;
    const int ec = (lane & 3) * 2;
#pragma unroll
    for (int fm = 0; fm < 2; fm++) {
#pragma unroll
        for (int fn = 0; fn < 8; fn++) {
            const int row = m0 + wm + fm * 16 + er;
            const int col = n0 + wn + fn * 8 + ec;
            const float bs0 = b1[col] + b2[col];
            const float bs1 = b1[col + 1] + b2[col + 1];
            float* p0 = XG + (size_t)row * G4 + col;
            float* p1 = XG + (size_t)(row + 8) * G4 + col;
            p0[0] = acc[fm][fn][0] + bs0;
            p0[1] = acc[fm][fn][1] + bs1;
            p1[0] = acc[fm][fn][2] + bs0;
            p1[1] = acc[fm][fn][3] + bs1;
        }
    }
}

// ---------------------------------------------------------------------------
// Persistent LSTM layer kernel: 128 CTAs x 256 threads, 256 steps in ONE launch.
// CTA jb owns h-cols j = jb*8..jb*8+7 -> 32 gate rows (local n = g*8+jj).
// w_hh hi/lo (32 rows x 1024, padded to 1032 hw) resident in smem all steps.
// c resident in smem. Steps separated by global counter barrier.
// gates[64b][32n] = h_hi*Whi + h_lo*Whi + h_hi*Wlo, k-chunk 64, double-buffered.
// ---------------------------------------------------------------------------
#define PADW 1032
#define PADA 72
// halfword offsets in dynamic smem
#define OFF_WHI 0
#define OFF_WLO (32 * PADW)                  // 33024
#define OFF_A   (2 * 32 * PADW)              // 66048
#define ATILE(buf, tl) (OFF_A + ((buf) * 2 + (tl)) * (64 * PADA))
#define OFF_GS_B ((OFF_A + 4 * 64 * PADA) * 2)   // byte offset of gs
#define OFF_C_B  (OFF_GS_B + 64 * 33 * 4)
#define PSMEM    (OFF_C_B + 64 * 8 * 4)          // 179456 bytes

__global__ __launch_bounds__(256)
void lstm_persistent(const float* __restrict__ xg,        // (T,B,4H)
                     const __nv_bfloat16* __restrict__ Whi,
                     const __nv_bfloat16* __restrict__ Wlo,
                     const float* __restrict__ res,       // (T,B,H)
                     float* __restrict__ outp,            // (T,B,H)
                     __nv_bfloat16* __restrict__ hhi,     // [2][B*H]
                     __nv_bfloat16* __restrict__ hlo,
                     int* __restrict__ ctr)               // [TT]
{
    extern __shared__ __align__(16) __nv_bfloat16 smh[];
    float* gs  = (float*)((char*)smh + OFF_GS_B);
    float* csm = (float*)((char*)smh + OFF_C_B);

    const int tid  = threadIdx.x;
    const int wid  = tid >> 5;
    const int lane = tid & 31;
    const int jb   = blockIdx.x;        // 0..127
    const int wm   = (wid & 3) * 16;    // batch offset
    const int wn   = (wid >> 2) * 16;   // gate-col offset

    const uint32_t smb = smem_u32(smh);
    const int a_r = lane & 15;
    const int a_c = (lane >> 4) * 8;
    const int b_r = ((lane >> 4) * 8) + (lane & 7);
    const int b_c = ((lane >> 3) & 1) * 8;

    // ---- load W tiles into smem (once) ----
#pragma unroll
    for (int i = 0; i < 16; i++) {
        const int idx = tid + i * 256;      // 0..4095 uint4 per tile
        const int row = idx >> 7;           // 0..31 local gate row
        const int seg = (idx & 127) * 8;    // halfword offset in row
        const size_t grow = (size_t)((row >> 3) * HH + jb * 8 + (row & 7)) * HH + seg;
        *(uint4*)&smh[OFF_WHI + row * PADW + seg] = *(const uint4*)(Whi + grow);
        *(uint4*)&smh[OFF_WLO + row * PADW + seg] = *(const uint4*)(Wlo + grow);
    }
    // zero c
    csm[tid] = 0.f;
    csm[tid + 256] = 0.f;
    __syncthreads();

    // staging role for A chunks: tile = tid>>7 (0=hi, 1=lo); 4 uint4 each
    const int stl = tid >> 7;
    const int sid = tid & 127;

    // pointwise mapping
    const int pb = tid >> 2;            // batch 0..63
    const int pj = (tid & 3) * 2;       // jj 0,2,4,6

    for (int t = 0; t < TT; t++) {
        const int pin  = t & 1;
        const __nv_bfloat16* hin = (stl ? hlo : hhi) + pin * (BB * HH);
        const float* xg_t  = xg  + (size_t)t * BB * G4;
        const float* res_t = res + (size_t)t * BB * HH;
        float*       out_t = outp + (size_t)t * BB * HH;

        float acc[2][4];
#pragma unroll
        for (int fn = 0; fn < 2; fn++)
#pragma unroll
            for (int q = 0; q < 4; q++) acc[fn][q] = 0.f;

        // prologue: stage chunk 0
#pragma unroll
        for (int i = 0; i < 4; i++) {
            const int id2 = sid + i * 128;
            const int row = id2 >> 3;
            const int seg = (id2 & 7) * 8;
            uint4 v = __ldcg((const uint4*)(hin + (size_t)row * HH + seg));
            *(uint4*)&smh[ATILE(0, stl) + row * PADA + seg] = v;
        }
        __syncthreads();

        for (int ch = 0; ch < 16; ch++) {
            const int buf = ch & 1;
            uint4 pf[4];
            if (ch + 1 < 16) {
                const int k0 = (ch + 1) * 64;
#pragma unroll
                for (int i = 0; i < 4; i++) {
                    const int id2 = sid + i * 128;
                    const int row = id2 >> 3;
                    const int seg = (id2 & 7) * 8;
                    pf[i] = __ldcg((const uint4*)(hin + (size_t)row * HH + k0 + seg));
                }
            }

#pragma unroll
            for (int kk = 0; kk < 4; kk++) {
                uint32_t ahi[4], alo[4];
                ldsm4(ahi, smb + (ATILE(buf, 0) + (wm + a_r) * PADA + kk * 16 + a_c) * 2);
                ldsm4(alo, smb + (ATILE(buf, 1) + (wm + a_r) * PADA + kk * 16 + a_c) * 2);
                const int wcol = ch * 64 + kk * 16 + b_c;
                uint32_t bh[4], bl[4];
                ldsm4(bh, smb + (OFF_WHI + (wn + b_r) * PADW + wcol) * 2);
                ldsm4(bl, smb + (OFF_WLO + (wn + b_r) * PADW + wcol) * 2);
                uint32_t bhi0[2] = {bh[0], bh[1]}, bhi1[2] = {bh[2], bh[3]};
                uint32_t blo0[2] = {bl[0], bl[1]}, blo1[2] = {bl[2], bl[3]};
                mma16816(acc[0], ahi, bhi0);
                mma16816(acc[0], alo, bhi0);
                mma16816(acc[0], ahi, blo0);
                mma16816(acc[1], ahi, bhi1);
                mma16816(acc[1], alo, bhi1);
                mma16816(acc[1], ahi, blo1);
            }

            if (ch + 1 < 16) {
                const int nb = buf ^ 1;
#pragma unroll
                for (int i = 0; i < 4; i++) {
                    const int id2 = sid + i * 128;
                    const int row = id2 >> 3;
                    const int seg = (id2 & 7) * 8;
                    *(uint4*)&smh[ATILE(nb, stl) + row * PADA + seg] = pf[i];
                }
            }
            __syncthreads();
        }

        // acc -> gs
        {
            const int er = lane >> 2;
            const int ec = (lane & 3) * 2;
#pragma unroll
            for (int fn = 0; fn < 2; fn++) {
                const int col = wn + fn * 8 + ec;
                gs[(wm + er) * 33 + col]         = acc[fn][0];
                gs[(wm + er) * 33 + col + 1]     = acc[fn][1];
                gs[(wm + er + 8) * 33 + col]     = acc[fn][2];
                gs[(wm + er + 8) * 33 + col + 1] = acc[fn][3];
            }
        }
        __syncthreads();

        // fused pointwise: 2 (b, jj) elems per thread
        {
            const size_t xb = (size_t)pb * G4 + jb * 8 + pj;
            float2 xi = *(const float2*)(xg_t + xb);
            float2 xf = *(const float2*)(xg_t + xb + HH);
            float2 xG = *(const float2*)(xg_t + xb + 2 * HH);
            float2 xo = *(const float2*)(xg_t + xb + 3 * HH);

            float i0 = gs[pb * 33 +      pj]     + xi.x;
            float i1 = gs[pb * 33 +      pj + 1] + xi.y;
            float f0 = gs[pb * 33 +  8 + pj]     + xf.x;
            float f1 = gs[pb * 33 +  8 + pj + 1] + xf.y;
            float q0 = gs[pb * 33 + 16 + pj]     + xG.x;
            float q1 = gs[pb * 33 + 16 + pj + 1] + xG.y;
            float o0 = gs[pb * 33 + 24 + pj]     + xo.x;
            float o1 = gs[pb * 33 + 24 + pj + 1] + xo.y;

            i0 = 1.f / (1.f + __expf(-i0));  i1 = 1.f / (1.f + __expf(-i1));
            f0 = 1.f / (1.f + __expf(-f0));  f1 = 1.f / (1.f + __expf(-f1));
            q0 = tanhf(q0);                  q1 = tanhf(q1);
            o0 = 1.f / (1.f + __expf(-o0));  o1 = 1.f / (1.f + __expf(-o1));

            const int ci = pb * 8 + pj;
            float c0 = f0 * csm[ci]     + i0 * q0;
            float c1 = f1 * csm[ci + 1] + i1 * q1;
            csm[ci]     = c0;
            csm[ci + 1] = c1;
            const float h0 = o0 * tanhf(c0);
            const float h1 = o1 * tanhf(c1);

            const size_t ho = (size_t)pb * HH + jb * 8 + pj;
            const int pout = pin ^ 1;
            __nv_bfloat16 h0h = __float2bfloat16(h0);
            __nv_bfloat16 h1h = __float2bfloat16(h1);
            __nv_bfloat162 hp; hp.x = h0h; hp.y = h1h;
            *(__nv_bfloat162*)(hhi + pout * (BB * HH) + ho) = hp;
            __nv_bfloat162 lp;
            lp.x = __float2bfloat16(h0 - __bfloat162float(h0h));
            lp.y = __float2bfloat16(h1 - __bfloat162float(h1h));
            *(__nv_bfloat162*)(hlo + pout * (BB * HH) + ho) = lp;

            float2 rv = *(const float2*)(res_t + ho);
            float2 ov; ov.x = h0 + rv.x; ov.y = h1 + rv.y;
            *(float2*)(out_t + ho) = ov;
        }

        // ---- global step barrier ----
        __threadfence();
        __syncthreads();
        if (tid == 0) {
            atomicAdd(ctr + t, 1);
            while (((volatile int*)ctr)[t] < NCT) __nanosleep(64);
            __threadfence();
        }
        __syncthreads();
    }
}

// ---------------------------------------------------------------------------
// Host launch
// ---------------------------------------------------------------------------
extern "C" void kernel_launch(void* const* d_in, const int* in_sizes, int n_in,
                              void* d_out, int out_size)
{
    (void)in_sizes; (void)n_in; (void)out_size;
    const float* x     = (const float*)d_in[0];
    const float* w_ih5 = (const float*)d_in[1];
    const float* w_hh5 = (const float*)d_in[2];
    const float* b_ih5 = (const float*)d_in[3];
    const float* b_hh5 = (const float*)d_in[4];
    const float* w_ih6 = (const float*)d_in[5];
    const float* w_hh6 = (const float*)d_in[6];
    const float* b_ih6 = (const float*)d_in[7];
    const float* b_hh6 = (const float*)d_in[8];
    float* out = (float*)d_out;

    float *xg, *out5;
    __nv_bfloat16 *ahi, *alo, *w5hi, *w5lo, *w6hi, *w6lo;
    __nv_bfloat16 *u5hi, *u5lo, *u6hi, *u6lo, *hhi, *hlo;
    int* ctr;
    cudaGetSymbolAddress((void**)&xg,   g_xg);
    cudaGetSymbolAddress((void**)&out5, g_out5);
    cudaGetSymbolAddress((void**)&ahi,  g_ahi);
    cudaGetSymbolAddress((void**)&alo,  g_alo);
    cudaGetSymbolAddress((void**)&w5hi, g_w5hi);
    cudaGetSymbolAddress((void**)&w5lo, g_w5lo);
    cudaGetSymbolAddress((void**)&w6hi, g_w6hi);
    cudaGetSymbolAddress((void**)&w6lo, g_w6lo);
    cudaGetSymbolAddress((void**)&u5hi, g_u5hi);
    cudaGetSymbolAddress((void**)&u5lo, g_u5lo);
    cudaGetSymbolAddress((void**)&u6hi, g_u6hi);
    cudaGetSymbolAddress((void**)&u6lo, g_u6lo);
    cudaGetSymbolAddress((void**)&hhi,  g_hhi);
    cudaGetSymbolAddress((void**)&hlo,  g_hlo);
    cudaGetSymbolAddress((void**)&ctr,  g_ctr);

    cudaFuncSetAttribute(lstm_persistent,
                         cudaFuncAttributeMaxDynamicSharedMemorySize, PSMEM);

    const dim3 gemm_grid(G4 / 128, MM / 128);

    // weight splits
    split_kernel<<<4096, 256>>>(w_ih5, w5hi, w5lo, G4 * HH);
    split_kernel<<<4096, 256>>>(w_ih6, w6hi, w6lo, G4 * HH);
    split_kernel<<<4096, 256>>>(w_hh5, u5hi, u5lo, G4 * HH);
    split_kernel<<<4096, 256>>>(w_hh6, u6hi, u6lo, G4 * HH);

    // ---- Layer 5 ----
    split_kernel<<<8192, 256>>>(x, ahi, alo, MM * HH);
    init_state_kernel<<<64, 1024>>>();
    gemm_mma_kernel<<<gemm_grid, 256>>>(ahi, alo, w5hi, w5lo, b_ih5, b_hh5, xg);
    lstm_persistent<<<NCT, 256, PSMEM>>>(xg, u5hi, u5lo, x, out5, hhi, hlo, ctr);

    // ---- Layer 6 ----
    split_kernel<<<8192, 256>>>(out5, ahi, alo, MM * HH);
    init_state_kernel<<<64, 1024>>>();
    gemm_mma_kernel<<<gemm_grid, 256>>>(ahi, alo, w6hi, w6lo, b_ih6, b_hh6, xg);
    lstm_persistent<<<NCT, 256, PSMEM>>>(xg, u6hi, u6lo, out5, out, hhi, hlo,
                                         ctr + TT);
}

// round 8
// speedup vs baseline: 3.0023x; 1.0586x over previous
#include <cuda_runtime.h>
#include <cuda_bf16.h>
#include <math.h>
#include <stdint.h>

#define TT 256
#define BB 64
#define HH 1024
#define G4 4096
#define MM (TT*BB)
#define NCT 128           // CTAs in persistent step kernel

// ---------------------------------------------------------------------------
// Scratch (device globals: allocation-free per harness rules)
// ---------------------------------------------------------------------------
__device__ float g_xg[(size_t)MM * G4];
__device__ float g_out5[(size_t)MM * HH];
__device__ __nv_bfloat16 g_hhi[2][BB * HH];
__device__ __nv_bfloat16 g_hlo[2][BB * HH];
__device__ __nv_bfloat16 g_ahi[(size_t)MM * HH];
__device__ __nv_bfloat16 g_alo[(size_t)MM * HH];
__device__ __nv_bfloat16 g_w5hi[(size_t)G4 * HH];
__device__ __nv_bfloat16 g_w5lo[(size_t)G4 * HH];
__device__ __nv_bfloat16 g_w6hi[(size_t)G4 * HH];
__device__ __nv_bfloat16 g_w6lo[(size_t)G4 * HH];
__device__ __nv_bfloat16 g_u5hi[(size_t)G4 * HH];
__device__ __nv_bfloat16 g_u5lo[(size_t)G4 * HH];
__device__ __nv_bfloat16 g_u6hi[(size_t)G4 * HH];
__device__ __nv_bfloat16 g_u6lo[(size_t)G4 * HH];
__device__ int g_ctr[2 * TT];

// ---------------------------------------------------------------------------
// mma.sync helpers
// ---------------------------------------------------------------------------
__device__ __forceinline__ uint32_t smem_u32(const void* p) {
    uint32_t a;
    asm("{ .reg .u64 t; cvta.to.shared.u64 t, %1; cvt.u32.u64 %0, t; }"
        : "=r"(a) : "l"(p));
    return a;
}
__device__ __forceinline__ void ldsm4(uint32_t* r, uint32_t addr) {
    asm volatile("ldmatrix.sync.aligned.m8n8.x4.shared.b16 {%0,%1,%2,%3}, [%4];"
                 : "=r"(r[0]), "=r"(r[1]), "=r"(r[2]), "=r"(r[3]) : "r"(addr));
}
__device__ __forceinline__ void ldsm2(uint32_t* r, uint32_t addr) {
    asm volatile("ldmatrix.sync.aligned.m8n8.x2.shared.b16 {%0,%1}, [%2];"
                 : "=r"(r[0]), "=r"(r[1]) : "r"(addr));
}
__device__ __forceinline__ void mma16816(float* d, const uint32_t* a,
                                         const uint32_t* b) {
    asm volatile(
        "mma.sync.aligned.m16n8k16.row.col.f32.bf16.bf16.f32 "
        "{%0,%1,%2,%3}, {%4,%5,%6,%7}, {%8,%9}, {%0,%1,%2,%3};"
        : "+f"(d[0]), "+f"(d[1]), "+f"(d[2]), "+f"(d[3])
        : "r"(a[0]), "r"(a[1]), "r"(a[2]), "r"(a[3]), "r"(b[0]), "r"(b[1]));
}

// ---------------------------------------------------------------------------
// hi/lo bf16 split
// ---------------------------------------------------------------------------
__global__ void split_kernel(const float* __restrict__ in,
                             __nv_bfloat16* __restrict__ hi,
                             __nv_bfloat16* __restrict__ lo, int n) {
    int i = blockIdx.x * blockDim.x + threadIdx.x;
    int stride = gridDim.x * blockDim.x;
    for (; i < n; i += stride) {
        float v = in[i];
        __nv_bfloat16 h = __float2bfloat16(v);
        float r = v - __bfloat162float(h);
        hi[i] = h;
        lo[i] = __float2bfloat16(r);
    }
}

__global__ void init_state_kernel() {
    int i = blockIdx.x * blockDim.x + threadIdx.x;
    if (i < BB * HH) {
        __nv_bfloat16 z = __float2bfloat16(0.f);
        g_hhi[0][i] = z; g_hhi[1][i] = z;
        g_hlo[0][i] = z; g_hlo[1][i] = z;
    }
    if (i < 2 * TT) g_ctr[i] = 0;
}

// ---------------------------------------------------------------------------
// Tensor-core input GEMM (R4/R5-verified, unchanged).
// ---------------------------------------------------------------------------
#define PAD 40
#define NCH 96

__global__ __launch_bounds__(256)
void gemm_mma_kernel(const __nv_bfloat16* __restrict__ Ahi,
                     const __nv_bfloat16* __restrict__ Alo,
                     const __nv_bfloat16* __restrict__ Bhi,
                     const __nv_bfloat16* __restrict__ Blo,
                     const float* __restrict__ b1,
                     const float* __restrict__ b2,
                     float* __restrict__ XG) {
    __shared__ __nv_bfloat16 As[2][128 * PAD];
    __shared__ __nv_bfloat16 Bs[2][128 * PAD];

    const int tid  = threadIdx.x;
    const int wid  = tid >> 5;
    const int lane = tid & 31;
    const int m0 = blockIdx.y * 128;
    const int n0 = blockIdx.x * 128;
    const int wm = (wid & 3) * 32;
    const int wn = (wid >> 2) * 64;

    float acc[2][8][4];
#pragma unroll
    for (int i = 0; i < 2; i++)
#pragma unroll
        for (int j = 0; j < 8; j++)
#pragma unroll
            for (int q = 0; q < 4; q++) acc[i][j][q] = 0.f;

    const int srow  = tid >> 1;
    const int skoff = (tid & 1) * 16;
    const uint32_t as_base = smem_u32(As);
    const uint32_t bs_base = smem_u32(Bs);

    const int a_r = lane & 15;
    const int a_c = (lane >> 4) * 8;
    const int b_r = ((lane >> 4) * 8) + (lane & 7);
    const int b_c = ((lane >> 3) & 1) * 8;

    {
        const uint4* a4 = (const uint4*)(Ahi + (size_t)(m0 + srow) * HH + skoff);
        const uint4* b4 = (const uint4*)(Bhi + (size_t)(n0 + srow) * HH + skoff);
        uint4 av0 = a4[0], av1 = a4[1];
        uint4 bv0 = b4[0], bv1 = b4[1];
        *(uint4*)&As[0][srow * PAD + skoff]     = av0;
        *(uint4*)&As[0][srow * PAD + skoff + 8] = av1;
        *(uint4*)&Bs[0][srow * PAD + skoff]     = bv0;
        *(uint4*)&Bs[0][srow * PAD + skoff + 8] = bv1;
    }
    __syncthreads();

    for (int c = 0; c < NCH; c++) {
        const int buf = c & 1;
        uint4 av0, av1, bv0, bv1;
        if (c + 1 < NCH) {
            const int cn  = c + 1;
            const int ph  = cn >> 5;
            const int kk0 = (cn & 31) * 32;
            const __nv_bfloat16* Ap = (ph == 1 ? Alo : Ahi);
            const __nv_bfloat16* Bp = (ph == 2 ? Blo : Bhi);
            const uint4* a4 = (const uint4*)(Ap + (size_t)(m0 + srow) * HH + kk0 + skoff);
            const uint4* b4 = (const uint4*)(Bp + (size_t)(n0 + srow) * HH + kk0 + skoff);
            av0 = a4[0]; av1 = a4[1];
            bv0 = b4[0]; bv1 = b4[1];
        }

#pragma unroll
        for (int kk = 0; kk < 2; kk++) {
            uint32_t afrag[2][4];
#pragma unroll
            for (int fm = 0; fm < 2; fm++) {
                const int row = wm + fm * 16 + a_r;
                const int col = kk * 16 + a_c;
                ldsm4(afrag[fm], as_base + (buf * 128 * PAD + row * PAD + col) * 2);
            }
            uint32_t bfrag[8][2];
#pragma unroll
            for (int fp = 0; fp < 4; fp++) {
                uint32_t r[4];
                const int row = wn + fp * 16 + b_r;
                const int col = kk * 16 + b_c;
                ldsm4(r, bs_base + (buf * 128 * PAD + row * PAD + col) * 2);
                bfrag[fp * 2][0]     = r[0];
                bfrag[fp * 2][1]     = r[1];
                bfrag[fp * 2 + 1][0] = r[2];
                bfrag[fp * 2 + 1][1] = r[3];
            }
#pragma unroll
            for (int fm = 0; fm < 2; fm++)
#pragma unroll
                for (int fn = 0; fn < 8; fn++)
                    mma16816(acc[fm][fn], afrag[fm], bfrag[fn]);
        }

        if (c + 1 < NCH) {
            const int nb = buf ^ 1;
            *(uint4*)&As[nb][srow * PAD + skoff]     = av0;
            *(uint4*)&As[nb][srow * PAD + skoff + 8] = av1;
            *(uint4*)&Bs[nb][srow * PAD + skoff]     = bv0;
            *(uint4*)&Bs[nb][srow * PAD + skoff + 8] = bv1;
        }
        __syncthreads();
    }

    const int er = lane >> 2;
    const int ec = (lane & 3) * 2;
#pragma unroll
    for (int fm = 0; fm < 2; fm++) {
#pragma unroll
        for (int fn = 0; fn < 8; fn++) {
            const int row = m0 + wm + fm * 16 + er;
            const int col = n0 + wn + fn * 8 + ec;
            const float bs0 = b1[col] + b2[col];
            const float bs1 = b1[col + 1] + b2[col + 1];
            float* p0 = XG + (size_t)row * G4 + col;
            float* p1 = XG + (size_t)(row + 8) * G4 + col;
            p0[0] = acc[fm][fn][0] + bs0;
            p0[1] = acc[fm][fn][1] + bs1;
            p1[0] = acc[fm][fn][2] + bs0;
            p1[1] = acc[fm][fn][3] + bs1;
        }
    }
}

// ---------------------------------------------------------------------------
// Persistent LSTM layer kernel v2: 128 CTAs x 512 threads (16 warps, 4/SMSP).
// CTA jb owns h-cols j = jb*8..jb*8+7 -> 32 gate rows. Warp tile m16 x n8.
// W hi/lo resident in smem; k-chunk 128 (8 chunks, 8 syncs); xg/res
// prefetched to regs at step start; c in a register.
// ---------------------------------------------------------------------------
#define PADW 1032
#define PADA 136
#define OFF_WHI 0
#define OFF_WLO (32 * PADW)
#define OFF_A   (2 * 32 * PADW)
#define ATILE(buf, tl) (OFF_A + ((buf) * 2 + (tl)) * (64 * PADA))
#define OFF_GS_B ((OFF_A + 4 * 64 * PADA) * 2)
#define PSMEM    (OFF_GS_B + 64 * 33 * 4)      // 210176 bytes

__global__ __launch_bounds__(512)
void lstm_persistent(const float* __restrict__ xg,
                     const __nv_bfloat16* __restrict__ Whi,
                     const __nv_bfloat16* __restrict__ Wlo,
                     const float* __restrict__ res,
                     float* __restrict__ outp,
                     __nv_bfloat16* __restrict__ hhi,
                     __nv_bfloat16* __restrict__ hlo,
                     int* __restrict__ ctr)
{
    extern __shared__ __align__(16) __nv_bfloat16 smh[];
    float* gs = (float*)((char*)smh + OFF_GS_B);

    const int tid  = threadIdx.x;
    const int wid  = tid >> 5;
    const int lane = tid & 31;
    const int jb   = blockIdx.x;
    const int wm   = (wid & 3) * 16;    // batch offset
    const int wn   = (wid >> 2) * 8;    // gate-col offset (16 warps: 0..24)

    const uint32_t smb = smem_u32(smh);
    const int a_r = lane & 15;
    const int a_c = (lane >> 4) * 8;
    const int w_r = lane & 7;           // x2: lanes 0-15 give addresses
    const int w_c = ((lane >> 3) & 1) * 8;

    // ---- load W tiles into smem (once) ----
#pragma unroll
    for (int i = 0; i < 8; i++) {
        const int idx = tid + i * 512;      // 0..4095 uint4 per tile
        const int row = idx >> 7;           // 0..31
        const int seg = (idx & 127) * 8;
        const size_t grow = (size_t)((row >> 3) * HH + jb * 8 + (row & 7)) * HH + seg;
        *(uint4*)&smh[OFF_WHI + row * PADW + seg] = *(const uint4*)(Whi + grow);
        *(uint4*)&smh[OFF_WLO + row * PADW + seg] = *(const uint4*)(Wlo + grow);
    }
    __syncthreads();

    // staging: tile = tid>>8 (0=hi, 1=lo), 4 uint4 per thread per chunk
    const int stl = tid >> 8;
    const int sid = tid & 255;
    const int srow = (sid >> 4) | 0;        // with i*256: idx>>4
    // pointwise mapping (fixed across steps)
    const int pb = tid >> 3;
    const int pj = tid & 7;
    const size_t ho = (size_t)pb * HH + jb * 8 + pj;
    const size_t xb = (size_t)pb * G4 + jb * 8 + pj;
    float creg = 0.f;

    for (int t = 0; t < TT; t++) {
        const int pin  = t & 1;
        const __nv_bfloat16* hin = (stl ? hlo : hhi) + pin * (BB * HH);
        const float* xg_t  = xg  + (size_t)t * BB * G4;
        const float* res_t = res + (size_t)t * BB * HH;
        float*       out_t = outp + (size_t)t * BB * HH;

        // prefetch pointwise inputs (independent of h) — hidden by mainloop
        const float xi = __ldg(xg_t + xb);
        const float xf = __ldg(xg_t + xb + HH);
        const float xq = __ldg(xg_t + xb + 2 * HH);
        const float xo = __ldg(xg_t + xb + 3 * HH);
        const float rv = __ldg(res_t + ho);

        float acc[4];
        acc[0] = acc[1] = acc[2] = acc[3] = 0.f;

        // stage chunk 0
#pragma unroll
        for (int i = 0; i < 4; i++) {
            const int idx = sid + i * 256;
            const int row = idx >> 4;
            const int seg = (idx & 15) * 8;
            uint4 v = __ldcg((const uint4*)(hin + (size_t)row * HH + seg));
            *(uint4*)&smh[ATILE(0, stl) + row * PADA + seg] = v;
        }
        __syncthreads();

        for (int ch = 0; ch < 8; ch++) {
            const int buf = ch & 1;
            uint4 pf[4];
            if (ch + 1 < 8) {
                const int k0 = (ch + 1) * 128;
#pragma unroll
                for (int i = 0; i < 4; i++) {
                    const int idx = sid + i * 256;
                    const int row = idx >> 4;
                    const int seg = (idx & 15) * 8;
                    pf[i] = __ldcg((const uint4*)(hin + (size_t)row * HH + k0 + seg));
                }
            }

#pragma unroll
            for (int kk = 0; kk < 8; kk++) {
                uint32_t ahi[4], alo[4];
                ldsm4(ahi, smb + (ATILE(buf, 0) + (wm + a_r) * PADA + kk * 16 + a_c) * 2);
                ldsm4(alo, smb + (ATILE(buf, 1) + (wm + a_r) * PADA + kk * 16 + a_c) * 2);
                const int wcol = ch * 128 + kk * 16 + w_c;
                uint32_t bh[2], bl[2];
                ldsm2(bh, smb + (OFF_WHI + (wn + w_r) * PADW + wcol) * 2);
                ldsm2(bl, smb + (OFF_WLO + (wn + w_r) * PADW + wcol) * 2);
                mma16816(acc, ahi, bh);
                mma16816(acc, alo, bh);
                mma16816(acc, ahi, bl);
            }

            if (ch + 1 < 8) {
                const int nb = buf ^ 1;
#pragma unroll
                for (int i = 0; i < 4; i++) {
                    const int idx = sid + i * 256;
                    const int row = idx >> 4;
                    const int seg = (idx & 15) * 8;
                    *(uint4*)&smh[ATILE(nb, stl) + row * PADA + seg] = pf[i];
                }
            }
            __syncthreads();
        }

        // acc -> gs  (warp m16 x n8)
        {
            const int er = lane >> 2;
            const int ec = (lane & 3) * 2;
            gs[(wm + er) * 33 + wn + ec]         = acc[0];
            gs[(wm + er) * 33 + wn + ec + 1]     = acc[1];
            gs[(wm + er + 8) * 33 + wn + ec]     = acc[2];
            gs[(wm + er + 8) * 33 + wn + ec + 1] = acc[3];
        }
        __syncthreads();

        // fused pointwise: 1 (b, jj) pair per thread
        {
            float i_ = gs[pb * 33 +      pj] + xi;
            float f_ = gs[pb * 33 +  8 + pj] + xf;
            float q_ = gs[pb * 33 + 16 + pj] + xq;
            float o_ = gs[pb * 33 + 24 + pj] + xo;

            i_ = 1.f / (1.f + __expf(-i_));
            f_ = 1.f / (1.f + __expf(-f_));
            q_ = tanhf(q_);
            o_ = 1.f / (1.f + __expf(-o_));

            creg = f_ * creg + i_ * q_;
            const float hv = o_ * tanhf(creg);

            const int pout = pin ^ 1;
            __nv_bfloat16 hh = __float2bfloat16(hv);
            hhi[pout * (BB * HH) + ho] = hh;
            hlo[pout * (BB * HH) + ho] =
                __float2bfloat16(hv - __bfloat162float(hh));
            out_t[ho] = hv + rv;
        }

        // ---- global step barrier ----
        __threadfence();
        __syncthreads();
        if (tid == 0) {
            atomicAdd(ctr + t, 1);
            while (((volatile int*)ctr)[t] < NCT) __nanosleep(64);
            __threadfence();
        }
        __syncthreads();
    }
}

// ---------------------------------------------------------------------------
// Host launch
// ---------------------------------------------------------------------------
extern "C" void kernel_launch(void* const* d_in, const int* in_sizes, int n_in,
                              void* d_out, int out_size)
{
    (void)in_sizes; (void)n_in; (void)out_size;
    const float* x     = (const float*)d_in[0];
    const float* w_ih5 = (const float*)d_in[1];
    const float* w_hh5 = (const float*)d_in[2];
    const float* b_ih5 = (const float*)d_in[3];
    const float* b_hh5 = (const float*)d_in[4];
    const float* w_ih6 = (const float*)d_in[5];
    const float* w_hh6 = (const float*)d_in[6];
    const float* b_ih6 = (const float*)d_in[7];
    const float* b_hh6 = (const float*)d_in[8];
    float* out = (float*)d_out;

    float *xg, *out5;
    __nv_bfloat16 *ahi, *alo, *w5hi, *w5lo, *w6hi, *w6lo;
    __nv_bfloat16 *u5hi, *u5lo, *u6hi, *u6lo, *hhi, *hlo;
    int* ctr;
    cudaGetSymbolAddress((void**)&xg,   g_xg);
    cudaGetSymbolAddress((void**)&out5, g_out5);
    cudaGetSymbolAddress((void**)&ahi,  g_ahi);
    cudaGetSymbolAddress((void**)&alo,  g_alo);
    cudaGetSymbolAddress((void**)&w5hi, g_w5hi);
    cudaGetSymbolAddress((void**)&w5lo, g_w5lo);
    cudaGetSymbolAddress((void**)&w6hi, g_w6hi);
    cudaGetSymbolAddress((void**)&w6lo, g_w6lo);
    cudaGetSymbolAddress((void**)&u5hi, g_u5hi);
    cudaGetSymbolAddress((void**)&u5lo, g_u5lo);
    cudaGetSymbolAddress((void**)&u6hi, g_u6hi);
    cudaGetSymbolAddress((void**)&u6lo, g_u6lo);
    cudaGetSymbolAddress((void**)&hhi,  g_hhi);
    cudaGetSymbolAddress((void**)&hlo,  g_hlo);
    cudaGetSymbolAddress((void**)&ctr,  g_ctr);

    cudaFuncSetAttribute(lstm_persistent,
                         cudaFuncAttributeMaxDynamicSharedMemorySize, PSMEM);

    const dim3 gemm_grid(G4 / 128, MM / 128);

    // weight splits
    split_kernel<<<4096, 256>>>(w_ih5, w5hi, w5lo, G4 * HH);
    split_kernel<<<4096, 256>>>(w_ih6, w6hi, w6lo, G4 * HH);
    split_kernel<<<4096, 256>>>(w_hh5, u5hi, u5lo, G4 * HH);
    split_kernel<<<4096, 256>>>(w_hh6, u6hi, u6lo, G4 * HH);

    // ---- Layer 5 ----
    split_kernel<<<8192, 256>>>(x, ahi, alo, MM * HH);
    init_state_kernel<<<64, 1024>>>();
    gemm_mma_kernel<<<gemm_grid, 256>>>(ahi, alo, w5hi, w5lo, b_ih5, b_hh5, xg);
    lstm_persistent<<<NCT, 512, PSMEM>>>(xg, u5hi, u5lo, x, out5, hhi, hlo, ctr);

    // ---- Layer 6 ----
    split_kernel<<<8192, 256>>>(out5, ahi, alo, MM * HH);
    init_state_kernel<<<64, 1024>>>();
    gemm_mma_kernel<<<gemm_grid, 256>>>(ahi, alo, w6hi, w6lo, b_ih6, b_hh6, xg);
    lstm_persistent<<<NCT, 512, PSMEM>>>(xg, u6hi, u6lo, out5, out, hhi, hlo,
                                         ctr + TT);
}